// round 15
// baseline (speedup 1.0000x reference)
#include <cuda_runtime.h>
#include <cuda_bf16.h>
#include <cstdint>
#include <math.h>

// ---------------------------------------------------------------------------
// Swin block, Round 15: hybrid pipeline depth — NS=3 (2 blk/SM) for deep-K
// GEMMs (qkv/fc1/fc2), NS=2 (3 blk/SM) for shallow-K (proj).
// Value-table mma attention (R12).
// ---------------------------------------------------------------------------

#define MTOK   100352
#define CCH    192
#define NHEAD  6
#define HEADD  32
#define WSZ    7
#define NTOK   49
#define HIDD   768
#define QKVC   576

typedef __nv_bfloat16 bf16;
typedef unsigned int u32;
typedef unsigned short u16;

// Scratch
__device__ bf16  g_ln1 [MTOK * CCH];
__device__ bf16  g_qkv [MTOK * QKVC];
__device__ bf16  g_att [MTOK * CCH];
__device__ bf16  g_proj[MTOK * CCH];
__device__ float g_x2  [MTOK * CCH];
__device__ bf16  g_ln2 [MTOK * CCH];
__device__ bf16  g_hid [MTOK * HIDD];
__device__ bf16  g_wq  [QKVC * CCH];
__device__ bf16  g_wp  [CCH * CCH];
__device__ bf16  g_w1  [HIDD * CCH];
__device__ bf16  g_w2  [CCH * HIDD];
__device__ float g_qbias[QKVC];
__device__ float g_vt  [64 * NHEAD * 4096];

__device__ __forceinline__ float warp_sum(float v) {
#pragma unroll
    for (int o = 16; o; o >>= 1) v += __shfl_xor_sync(0xffffffffu, v, o);
    return v;
}

__device__ __forceinline__ u32 smem_u32(const void* p) {
    u32 a;
    asm("{ .reg .u64 t; cvta.to.shared.u64 t, %1; cvt.u32.u64 %0, t; }"
        : "=r"(a) : "l"(p));
    return a;
}

__device__ __forceinline__ void ldsm4(u32& r0, u32& r1, u32& r2, u32& r3, u32 a) {
    asm volatile("ldmatrix.sync.aligned.m8n8.x4.shared.b16 {%0,%1,%2,%3},[%4];"
                 : "=r"(r0), "=r"(r1), "=r"(r2), "=r"(r3) : "r"(a));
}

__device__ __forceinline__ void cp16(u32 dst, const void* src) {
    asm volatile("cp.async.cg.shared.global [%0],[%1],16;" :: "r"(dst), "l"(src));
}

__device__ __forceinline__ void mma16816(float* d, const u32* a, const u32* b) {
    asm volatile(
        "mma.sync.aligned.m16n8k16.row.col.f32.bf16.bf16.f32 "
        "{%0,%1,%2,%3},{%4,%5,%6,%7},{%8,%9},{%0,%1,%2,%3};"
        : "+f"(d[0]), "+f"(d[1]), "+f"(d[2]), "+f"(d[3])
        : "r"(a[0]), "r"(a[1]), "r"(a[2]), "r"(a[3]), "r"(b[0]), "r"(b[1]));
}

__device__ __forceinline__ u32 packbf2(float lo, float hi) {
    __nv_bfloat162 t = __floats2bfloat162_rn(lo, hi);
    return *(u32*)&t;
}

// ---------------------------------------------------------------------------
// Kernel 0: weights fp32 -> bf16 (q rows pre-scaled); q bias scaled
// ---------------------------------------------------------------------------
__global__ void convert_weights(const float* __restrict__ qw,
                                const float* __restrict__ qb,
                                const float* __restrict__ pw,
                                const float* __restrict__ w1,
                                const float* __restrict__ w2) {
    const float scale = 0.17677669529663687f;
    int i = blockIdx.x * 256 + threadIdx.x;
    if (i < QKVC * CCH) {
        float v = qw[i];
        if (i < CCH * CCH) v *= scale;
        g_wq[i] = __float2bfloat16(v);
    }
    if (i < CCH * CCH)  g_wp[i] = __float2bfloat16(pw[i]);
    if (i < HIDD * CCH) g_w1[i] = __float2bfloat16(w1[i]);
    if (i < CCH * HIDD) g_w2[i] = __float2bfloat16(w2[i]);
    if (i < QKVC) g_qbias[i] = qb[i] * (i < CCH ? scale : 1.0f);
}

// ---------------------------------------------------------------------------
// Kernel 0b: per-(window,head) bias+mask value table (fp32)
// ---------------------------------------------------------------------------
__global__ void build_vt_kernel(const float* __restrict__ bias_table) {
    int win = blockIdx.x, h = blockIdx.y;
    float* dst = g_vt + ((size_t)(win * NHEAD) + h) * 4096;
    for (int e = threadIdx.x; e < 4096; e += 256) {
        int i = e >> 6, j = e & 63;
        float v;
        if (j >= NTOK) {
            v = -1e30f;
        } else {
            int ii = i < NTOK ? i : 0;
            int idx = (ii / 7 - j / 7 + 6) * 13 + (ii % 7 - j % 7 + 6);
            float b = bias_table[idx * NHEAD + h];
            int hi2 = (win >> 3) * WSZ + ii / 7, wi2 = (win & 7) * WSZ + ii % 7;
            int hj2 = (win >> 3) * WSZ + j / 7,  wj2 = (win & 7) * WSZ + j % 7;
            int ra = (hi2 < 49 ? 0 : (hi2 < 53 ? 1 : 2)) * 3 + (wi2 < 49 ? 0 : (wi2 < 53 ? 1 : 2));
            int rb = (hj2 < 49 ? 0 : (hj2 < 53 ? 1 : 2)) * 3 + (wj2 < 49 ? 0 : (wj2 < 53 ? 1 : 2));
            v = b + (ra != rb ? -100.0f : 0.0f);
        }
        dst[e] = v;
    }
}

// ---------------------------------------------------------------------------
// Kernel 1: LN1 + cyclic shift + window partition -> bf16. One warp per token.
// ---------------------------------------------------------------------------
__global__ void ln_shift_gather_kernel(const float* __restrict__ x,
                                       const float* __restrict__ g1,
                                       const float* __restrict__ b1) {
    int m = (blockIdx.x * blockDim.x + threadIdx.x) >> 5;
    int lane = threadIdx.x & 31;
    if (m >= MTOK) return;

    int wb  = m / NTOK;
    int n   = m - wb * NTOK;
    int bi  = wb >> 6;
    int win = wb & 63;
    int hs = (win >> 3) * WSZ + n / WSZ;
    int ws = (win & 7)  * WSZ + n % WSZ;
    int hh = hs + 3; if (hh >= 56) hh -= 56;
    int ww = ws + 3; if (ww >= 56) ww -= 56;

    const float* src = x + ((size_t)bi * 3136 + hh * 56 + ww) * CCH;
    float v[6];
    float s = 0.f;
#pragma unroll
    for (int i = 0; i < 6; i++) { v[i] = src[lane + 32 * i]; s += v[i]; }
    s = warp_sum(s);
    float mu = s * (1.0f / CCH);
    float q = 0.f;
#pragma unroll
    for (int i = 0; i < 6; i++) { float d = v[i] - mu; q += d * d; }
    q = warp_sum(q);
    float rstd = rsqrtf(q * (1.0f / CCH) + 1e-5f);

    bf16* dst = g_ln1 + (size_t)m * CCH;
#pragma unroll
    for (int i = 0; i < 6; i++) {
        int c = lane + 32 * i;
        dst[c] = __float2bfloat16((v[i] - mu) * rstd * g1[c] + b1[c]);
    }
}

// ---------------------------------------------------------------------------
// bf16 tensor-core GEMM: BM=128 BN=96 BK=64, NS-stage cp.async pipeline.
// NS=2 -> 3 blocks/SM (R12 schedule); NS=3 -> 2 blocks/SM (R14 schedule).
// EPI: 0 bias->OutT, 1 bias+GELU->OutT, 2 bias+res(fp32)->OutT
// ---------------------------------------------------------------------------
template <int NS, int EPI, typename OutT>
__global__ __launch_bounds__(256, NS == 2 ? 3 : 2) void bf16_gemm_kernel(
        const bf16* __restrict__ A,
        const bf16* __restrict__ W,
        const float* __restrict__ bias,
        OutT* __restrict__ C,
        const float* __restrict__ res,
        int M, int N, int K) {
    const int BM = 128, BN = 96, BK = 64, LDA = 72;
    const int STAGE_H = (BM + BN) * LDA;
    extern __shared__ bf16 smem[];

    int t = threadIdx.x;
    int bm = blockIdx.y * BM, bn = blockIdx.x * BN;
    int warp = t >> 5, lane = t & 31;
    int wm = (warp & 3) * 32, wn = (warp >> 2) * 48;
    int qr = lane >> 2, qc = lane & 3;

    u32 sbase = smem_u32(smem);

    int arow = t >> 1, ahalf = t & 1;
    const bf16* Ag = A + (size_t)(bm + arow) * K + ahalf * 32;
    u32 adst = sbase + (arow * LDA + ahalf * 32) * 2;
    int brow = t >> 1, bhalf = t & 1;
    const bf16* Wg = W + (size_t)(bn + brow) * K + bhalf * 32;
    u32 bdst = sbase + ((BM + brow) * LDA + bhalf * 32) * 2;
    bool hasb = (t < 192);

    int l15 = lane & 15, lhi = lane >> 4;
    u32 aoff = ((wm + l15) * LDA + lhi * 8) * 2;
    int bl = (lane & 7) + ((lane & 16) ? 8 : 0);
    int bkc = (lane >> 3) & 1;
    u32 boff = ((BM + wn + bl) * LDA + bkc * 8) * 2;

    float acc[2][6][4];
#pragma unroll
    for (int i = 0; i < 2; i++)
#pragma unroll
        for (int j = 0; j < 6; j++)
#pragma unroll
            for (int e = 0; e < 4; e++) acc[i][j][e] = 0.f;

    const u32 STB = STAGE_H * 2;
    int nk = K / BK;

    if (NS == 2) {
        // R12 schedule: double buffer, wait_group 0
#pragma unroll
        for (int j = 0; j < 4; j++) cp16(adst + j * 16, Ag + j * 8);
        if (hasb) {
#pragma unroll
            for (int j = 0; j < 4; j++) cp16(bdst + j * 16, Wg + j * 8);
        }
        asm volatile("cp.async.commit_group;" ::: "memory");

        for (int i = 0; i < nk; i++) {
            asm volatile("cp.async.wait_group 0;" ::: "memory");
            __syncthreads();

            if (i + 1 < nk) {
                u32 so = (u32)((i + 1) & 1) * STB;
                int k0 = (i + 1) * BK;
#pragma unroll
                for (int j = 0; j < 4; j++) cp16(adst + so + j * 16, Ag + k0 + j * 8);
                if (hasb) {
#pragma unroll
                    for (int j = 0; j < 4; j++) cp16(bdst + so + j * 16, Wg + k0 + j * 8);
                }
                asm volatile("cp.async.commit_group;" ::: "memory");
            }

            u32 so = (u32)(i & 1) * STB;
#pragma unroll
            for (int kk = 0; kk < 4; kk++) {
                u32 kb = kk * 32;
                u32 am[2][4];
                ldsm4(am[0][0], am[0][1], am[0][2], am[0][3], sbase + so + aoff + kb);
                ldsm4(am[1][0], am[1][1], am[1][2], am[1][3],
                      sbase + so + aoff + 16 * LDA * 2 + kb);
                u32 b[6][2];
#pragma unroll
                for (int g = 0; g < 3; g++)
                    ldsm4(b[2 * g][0], b[2 * g][1], b[2 * g + 1][0], b[2 * g + 1][1],
                          sbase + so + boff + (u32)(g * 16 * LDA * 2) + kb);
#pragma unroll
                for (int mi = 0; mi < 2; mi++)
#pragma unroll
                    for (int ni = 0; ni < 6; ni++)
                        mma16816(acc[mi][ni], am[mi], b[ni]);
            }
        }
    } else {
        // R14 schedule: NS=3, wait_group 1, unconditional commit
#pragma unroll
        for (int p = 0; p < NS - 1; p++) {
            if (p < nk) {
                u32 so = (u32)p * STB;
                int k0 = p * BK;
#pragma unroll
                for (int j = 0; j < 4; j++) cp16(adst + so + j * 16, Ag + k0 + j * 8);
                if (hasb) {
#pragma unroll
                    for (int j = 0; j < 4; j++) cp16(bdst + so + j * 16, Wg + k0 + j * 8);
                }
            }
            asm volatile("cp.async.commit_group;" ::: "memory");
        }

        int buf = 0;
        for (int i = 0; i < nk; i++) {
            asm volatile("cp.async.wait_group 1;" ::: "memory");
            __syncthreads();

            int nx = i + NS - 1;
            if (nx < nk) {
                u32 so = (u32)(nx % NS) * STB;
                int k0 = nx * BK;
#pragma unroll
                for (int j = 0; j < 4; j++) cp16(adst + so + j * 16, Ag + k0 + j * 8);
                if (hasb) {
#pragma unroll
                    for (int j = 0; j < 4; j++) cp16(bdst + so + j * 16, Wg + k0 + j * 8);
                }
            }
            asm volatile("cp.async.commit_group;" ::: "memory");

            u32 so = (u32)buf * STB;
#pragma unroll
            for (int kk = 0; kk < 4; kk++) {
                u32 kb = kk * 32;
                u32 am[2][4];
                ldsm4(am[0][0], am[0][1], am[0][2], am[0][3], sbase + so + aoff + kb);
                ldsm4(am[1][0], am[1][1], am[1][2], am[1][3],
                      sbase + so + aoff + 16 * LDA * 2 + kb);
                u32 b[6][2];
#pragma unroll
                for (int g = 0; g < 3; g++)
                    ldsm4(b[2 * g][0], b[2 * g][1], b[2 * g + 1][0], b[2 * g + 1][1],
                          sbase + so + boff + (u32)(g * 16 * LDA * 2) + kb);
#pragma unroll
                for (int mi = 0; mi < 2; mi++)
#pragma unroll
                    for (int ni = 0; ni < 6; ni++)
                        mma16816(acc[mi][ni], am[mi], b[ni]);
            }
            buf = (buf + 1 < NS) ? buf + 1 : 0;
        }
        asm volatile("cp.async.wait_group 0;" ::: "memory");
    }

    // epilogue: packed pair stores
#pragma unroll
    for (int mi = 0; mi < 2; mi++) {
#pragma unroll
        for (int ni = 0; ni < 6; ni++) {
            int row = bm + wm + mi * 16 + qr;
            int col = bn + wn + ni * 8 + qc * 2;
            float b0 = bias[col], b1v = bias[col + 1];
#pragma unroll
            for (int rh = 0; rh < 2; rh++) {
                int r = row + rh * 8;
                float v0 = acc[mi][ni][rh * 2]     + b0;
                float v1 = acc[mi][ni][rh * 2 + 1] + b1v;
                if (EPI == 1) {
                    v0 = 0.5f * v0 * (1.0f + erff(v0 * 0.70710678118654752f));
                    v1 = 0.5f * v1 * (1.0f + erff(v1 * 0.70710678118654752f));
                }
                if (EPI == 2) {
                    float2 rv = *(const float2*)(res + (size_t)r * N + col);
                    v0 += rv.x; v1 += rv.y;
                }
                if (sizeof(OutT) == 2) {
                    *(u32*)((bf16*)C + (size_t)r * N + col) = packbf2(v0, v1);
                } else {
                    float2 tv; tv.x = v0; tv.y = v1;
                    *(float2*)((float*)C + (size_t)r * N + col) = tv;
                }
            }
        }
    }
}

// ---------------------------------------------------------------------------
// Kernel 3: mma attention with precomputed value table (R12, unchanged).
// ---------------------------------------------------------------------------
__global__ __launch_bounds__(64) void attn_mma_kernel() {
    __shared__ __align__(16) bf16 qs[2][64 * 40];
    __shared__ __align__(16) bf16 ks[2][64 * 40];
    __shared__ __align__(16) bf16 vts[2][32 * 72];

    int tid = threadIdx.x, w = tid >> 5, lane = tid & 31;
    int wb = blockIdx.x, win = wb & 63;
    int h = blockIdx.y * 2 + w;

    u32 sq = smem_u32(qs[w]);
    u32 sk = smem_u32(ks[w]);
    u32 sv = smem_u32(vts[w]);

    const bf16* qbase = g_qkv + (size_t)(wb * NTOK) * QKVC + h * HEADD;
    for (int u = lane; u < 196; u += 32) {
        int n = u >> 2, c = u & 3;
        cp16(sq + n * 80 + c * 16, qbase + (size_t)n * QKVC + c * 8);
        cp16(sk + n * 80 + c * 16, qbase + (size_t)n * QKVC + CCH + c * 8);
    }
    asm volatile("cp.async.commit_group;" ::: "memory");

    {
        u32* qz = (u32*)qs[w];
        u32* kz = (u32*)ks[w];
        for (int u = lane; u < 300; u += 32) {
            int idx = (NTOK + u / 20) * 20 + u % 20;
            qz[idx] = 0; kz[idx] = 0;
        }
        u32* vz = (u32*)vts[w];
        for (int u = lane; u < 1152; u += 32) vz[u] = 0;
    }

    {
        const bf16* vbase = qbase + 2 * CCH;
        for (int u = lane; u < 784; u += 32) {
            int j = u >> 4, dd = u & 15;
            u32 pv = *(const u32*)(vbase + (size_t)j * QKVC + 2 * dd);
            vts[w][(2 * dd) * 72 + j]     = ((bf16*)&pv)[0];
            vts[w][(2 * dd + 1) * 72 + j] = ((bf16*)&pv)[1];
        }
    }

    asm volatile("cp.async.wait_group 0;" ::: "memory");
    __syncthreads();

    int qr = lane >> 2, qc = lane & 3;
    int l15 = lane & 15, lhi = lane >> 4;
    u32 aoff = (u32)((l15 * 40 + lhi * 8) * 2);
    int blr = (lane & 7) + ((lane & 16) ? 8 : 0);
    int bkc = (lane >> 3) & 1;
    u32 bKoff = (u32)((blr * 40 + bkc * 8) * 2);
    u32 bVoff = (u32)((blr * 72 + bkc * 8) * 2);

    const float* vtp = g_vt + ((size_t)(win * NHEAD) + h) * 4096;
    bf16* opbase = g_att + (size_t)(wb * NTOK) * CCH + h * HEADD;

#pragma unroll
    for (int mh = 0; mh < 2; mh++) {
        int m0 = mh * 32;
        float acc[2][8][4];
#pragma unroll
        for (int a = 0; a < 2; a++)
#pragma unroll
            for (int b = 0; b < 8; b++)
#pragma unroll
                for (int e = 0; e < 4; e++) acc[a][b][e] = 0.f;

#pragma unroll
        for (int kk = 0; kk < 2; kk++) {
            u32 kb = kk * 32;
            u32 am[2][4];
            ldsm4(am[0][0], am[0][1], am[0][2], am[0][3], sq + aoff + (u32)(m0 * 80) + kb);
            ldsm4(am[1][0], am[1][1], am[1][2], am[1][3], sq + aoff + (u32)((m0 + 16) * 80) + kb);
            u32 b[8][2];
#pragma unroll
            for (int np = 0; np < 4; np++)
                ldsm4(b[2 * np][0], b[2 * np][1], b[2 * np + 1][0], b[2 * np + 1][1],
                      sk + bKoff + (u32)(np * 16 * 80) + kb);
#pragma unroll
            for (int mi = 0; mi < 2; mi++)
#pragma unroll
                for (int ni = 0; ni < 8; ni++)
                    mma16816(acc[mi][ni], am[mi], b[ni]);
        }

#pragma unroll
        for (int mi = 0; mi < 2; mi++)
#pragma unroll
            for (int ni = 0; ni < 8; ni++) {
                int c = ni * 8 + 2 * qc;
#pragma unroll
                for (int rh = 0; rh < 2; rh++) {
                    int r = m0 + mi * 16 + qr + rh * 8;
                    float2 bv = *(const float2*)(vtp + r * 64 + c);
                    acc[mi][ni][rh * 2]     += bv.x;
                    acc[mi][ni][rh * 2 + 1] += bv.y;
                }
            }

#pragma unroll
        for (int mi = 0; mi < 2; mi++)
#pragma unroll
            for (int rh = 0; rh < 2; rh++) {
                float mx = -1e30f;
#pragma unroll
                for (int ni = 0; ni < 8; ni++)
#pragma unroll
                    for (int el = 0; el < 2; el++)
                        mx = fmaxf(mx, acc[mi][ni][rh * 2 + el]);
                mx = fmaxf(mx, __shfl_xor_sync(0xffffffffu, mx, 1));
                mx = fmaxf(mx, __shfl_xor_sync(0xffffffffu, mx, 2));
                float sum = 0.f;
#pragma unroll
                for (int ni = 0; ni < 8; ni++)
#pragma unroll
                    for (int el = 0; el < 2; el++) {
                        float p = __expf(acc[mi][ni][rh * 2 + el] - mx);
                        acc[mi][ni][rh * 2 + el] = p;
                        sum += p;
                    }
                sum += __shfl_xor_sync(0xffffffffu, sum, 1);
                sum += __shfl_xor_sync(0xffffffffu, sum, 2);
                float inv = 1.0f / sum;
#pragma unroll
                for (int ni = 0; ni < 8; ni++)
#pragma unroll
                    for (int el = 0; el < 2; el++)
                        acc[mi][ni][rh * 2 + el] *= inv;
            }

        u32 pa[2][4][4];
#pragma unroll
        for (int mi = 0; mi < 2; mi++)
#pragma unroll
            for (int kt = 0; kt < 4; kt++) {
                pa[mi][kt][0] = packbf2(acc[mi][2 * kt][0],     acc[mi][2 * kt][1]);
                pa[mi][kt][1] = packbf2(acc[mi][2 * kt][2],     acc[mi][2 * kt][3]);
                pa[mi][kt][2] = packbf2(acc[mi][2 * kt + 1][0], acc[mi][2 * kt + 1][1]);
                pa[mi][kt][3] = packbf2(acc[mi][2 * kt + 1][2], acc[mi][2 * kt + 1][3]);
            }

        float o[2][4][4];
#pragma unroll
        for (int a = 0; a < 2; a++)
#pragma unroll
            for (int b = 0; b < 4; b++)
#pragma unroll
                for (int e = 0; e < 4; e++) o[a][b][e] = 0.f;
#pragma unroll
        for (int kt = 0; kt < 4; kt++) {
            u32 bv[4][2];
            ldsm4(bv[0][0], bv[0][1], bv[1][0], bv[1][1], sv + bVoff + (u32)(kt * 32));
            ldsm4(bv[2][0], bv[2][1], bv[3][0], bv[3][1],
                  sv + bVoff + (u32)(16 * 144) + (u32)(kt * 32));
#pragma unroll
            for (int mi = 0; mi < 2; mi++)
#pragma unroll
                for (int nv = 0; nv < 4; nv++)
                    mma16816(o[mi][nv], pa[mi][kt], bv[nv]);
        }

#pragma unroll
        for (int mi = 0; mi < 2; mi++)
#pragma unroll
            for (int rh = 0; rh < 2; rh++) {
                int r = m0 + mi * 16 + qr + rh * 8;
                if (r < NTOK) {
#pragma unroll
                    for (int nv = 0; nv < 4; nv++) {
                        u32 pk = packbf2(o[mi][nv][rh * 2], o[mi][nv][rh * 2 + 1]);
                        *(u32*)(opbase + (size_t)r * CCH + nv * 8 + 2 * qc) = pk;
                    }
                }
            }
    }
}

// ---------------------------------------------------------------------------
// Kernel 4: window reverse + unshift + residual + LN2. (proj bf16)
// ---------------------------------------------------------------------------
__global__ void reverse_add_ln2_kernel(const float* __restrict__ x,
                                       const float* __restrict__ g2,
                                       const float* __restrict__ b2) {
    int m = (blockIdx.x * blockDim.x + threadIdx.x) >> 5;
    int lane = threadIdx.x & 31;
    if (m >= MTOK) return;

    int wb  = m / NTOK;
    int n   = m - wb * NTOK;
    int bi  = wb >> 6;
    int win = wb & 63;
    int hs = (win >> 3) * WSZ + n / WSZ;
    int ws = (win & 7)  * WSZ + n % WSZ;
    int hh = hs + 3; if (hh >= 56) hh -= 56;
    int ww = ws + 3; if (ww >= 56) ww -= 56;
    size_t tt = (size_t)bi * 3136 + hh * 56 + ww;

    const float* xs = x + tt * CCH;
    const bf16* pr = g_proj + (size_t)m * CCH;
    float* x2 = g_x2 + tt * CCH;
    bf16* hl  = g_ln2 + tt * CCH;

    float v[6];
    float s = 0.f;
#pragma unroll
    for (int i = 0; i < 6; i++) {
        int c = lane + 32 * i;
        v[i] = xs[c] + __bfloat162float(pr[c]);
        x2[c] = v[i];
        s += v[i];
    }
    s = warp_sum(s);
    float mu = s * (1.0f / CCH);
    float q = 0.f;
#pragma unroll
    for (int i = 0; i < 6; i++) { float d = v[i] - mu; q += d * d; }
    q = warp_sum(q);
    float rstd = rsqrtf(q * (1.0f / CCH) + 1e-5f);
#pragma unroll
    for (int i = 0; i < 6; i++) {
        int c = lane + 32 * i;
        hl[c] = __float2bfloat16((v[i] - mu) * rstd * g2[c] + b2[c]);
    }
}

// ---------------------------------------------------------------------------
// Host launcher
// ---------------------------------------------------------------------------
extern "C" void kernel_launch(void* const* d_in, const int* in_sizes, int n_in,
                              void* d_out, int out_size) {
    const float* x          = (const float*)d_in[0];
    const float* g1         = (const float*)d_in[1];
    const float* b1         = (const float*)d_in[2];
    const float* qkv_w      = (const float*)d_in[3];
    const float* qkv_b      = (const float*)d_in[4];
    const float* proj_w     = (const float*)d_in[5];
    const float* proj_b     = (const float*)d_in[6];
    const float* bias_table = (const float*)d_in[7];
    const float* g2         = (const float*)d_in[8];
    const float* b2         = (const float*)d_in[9];
    const float* fc1_w      = (const float*)d_in[10];
    const float* fc1_b      = (const float*)d_in[11];
    const float* fc2_w      = (const float*)d_in[12];
    const float* fc2_b      = (const float*)d_in[13];
    float* out = (float*)d_out;

    bf16 *p_ln1, *p_qkvb, *p_att, *p_proj, *p_ln2, *p_hid, *p_wq, *p_wp, *p_w1, *p_w2;
    float *p_x2, *p_qbias;
    cudaGetSymbolAddress((void**)&p_ln1,  g_ln1);
    cudaGetSymbolAddress((void**)&p_qkvb, g_qkv);
    cudaGetSymbolAddress((void**)&p_att,  g_att);
    cudaGetSymbolAddress((void**)&p_proj, g_proj);
    cudaGetSymbolAddress((void**)&p_x2,   g_x2);
    cudaGetSymbolAddress((void**)&p_ln2,  g_ln2);
    cudaGetSymbolAddress((void**)&p_hid,  g_hid);
    cudaGetSymbolAddress((void**)&p_wq,   g_wq);
    cudaGetSymbolAddress((void**)&p_wp,   g_wp);
    cudaGetSymbolAddress((void**)&p_w1,   g_w1);
    cudaGetSymbolAddress((void**)&p_w2,   g_w2);
    cudaGetSymbolAddress((void**)&p_qbias, g_qbias);

    const int SMEM2 = 2 * (128 + 96) * 72 * 2;   // 64512 bytes
    const int SMEM3 = 3 * (128 + 96) * 72 * 2;   // 96768 bytes
    cudaFuncSetAttribute(bf16_gemm_kernel<3, 0, bf16>,
                         cudaFuncAttributeMaxDynamicSharedMemorySize, SMEM3);
    cudaFuncSetAttribute(bf16_gemm_kernel<2, 0, bf16>,
                         cudaFuncAttributeMaxDynamicSharedMemorySize, SMEM2);
    cudaFuncSetAttribute(bf16_gemm_kernel<3, 1, bf16>,
                         cudaFuncAttributeMaxDynamicSharedMemorySize, SMEM3);
    cudaFuncSetAttribute(bf16_gemm_kernel<3, 2, float>,
                         cudaFuncAttributeMaxDynamicSharedMemorySize, SMEM3);

    convert_weights<<<576, 256>>>(qkv_w, qkv_b, proj_w, fc1_w, fc2_w);
    build_vt_kernel<<<dim3(64, NHEAD), 256>>>(bias_table);

    ln_shift_gather_kernel<<<MTOK / 8, 256>>>(x, g1, b1);

    // qkv: nk=3 -> NS=3
    bf16_gemm_kernel<3, 0, bf16><<<dim3(QKVC / 96, MTOK / 128), 256, SMEM3>>>(
        p_ln1, p_wq, p_qbias, p_qkvb, nullptr, MTOK, QKVC, CCH);

    attn_mma_kernel<<<dim3(MTOK / NTOK, NHEAD / 2), 64>>>();

    // proj: nk=2 -> NS=2 (occupancy 3 blocks)
    bf16_gemm_kernel<2, 0, bf16><<<dim3(CCH / 96, MTOK / 128), 256, SMEM2>>>(
        p_att, p_wp, proj_b, p_proj, nullptr, MTOK, CCH, CCH);

    reverse_add_ln2_kernel<<<MTOK / 8, 256>>>(x, g2, b2);

    // fc1: nk=3 -> NS=3
    bf16_gemm_kernel<3, 1, bf16><<<dim3(HIDD / 96, MTOK / 128), 256, SMEM3>>>(
        p_ln2, p_w1, fc1_b, p_hid, nullptr, MTOK, HIDD, CCH);

    // fc2: nk=12 -> NS=3
    bf16_gemm_kernel<3, 2, float><<<dim3(CCH / 96, MTOK / 128), 256, SMEM3>>>(
        p_hid, p_w2, fc2_b, out, p_x2, MTOK, CCH, HIDD);
}

// round 16
// speedup vs baseline: 1.0264x; 1.0264x over previous
#include <cuda_runtime.h>
#include <cuda_bf16.h>
#include <cstdint>
#include <math.h>

// ---------------------------------------------------------------------------
// Swin block, Round 16: R12 baseline (all NS=2, 3 blk/SM) with the single
// validated delta: qkv GEMM uses the NS=3 schedule (measured -6.5us).
// Value-table mma attention (R12).
// ---------------------------------------------------------------------------

#define MTOK   100352
#define CCH    192
#define NHEAD  6
#define HEADD  32
#define WSZ    7
#define NTOK   49
#define HIDD   768
#define QKVC   576

typedef __nv_bfloat16 bf16;
typedef unsigned int u32;
typedef unsigned short u16;

// Scratch
__device__ bf16  g_ln1 [MTOK * CCH];
__device__ bf16  g_qkv [MTOK * QKVC];
__device__ bf16  g_att [MTOK * CCH];
__device__ bf16  g_proj[MTOK * CCH];
__device__ float g_x2  [MTOK * CCH];
__device__ bf16  g_ln2 [MTOK * CCH];
__device__ bf16  g_hid [MTOK * HIDD];
__device__ bf16  g_wq  [QKVC * CCH];
__device__ bf16  g_wp  [CCH * CCH];
__device__ bf16  g_w1  [HIDD * CCH];
__device__ bf16  g_w2  [CCH * HIDD];
__device__ float g_qbias[QKVC];
__device__ float g_vt  [64 * NHEAD * 4096];

__device__ __forceinline__ float warp_sum(float v) {
#pragma unroll
    for (int o = 16; o; o >>= 1) v += __shfl_xor_sync(0xffffffffu, v, o);
    return v;
}

__device__ __forceinline__ u32 smem_u32(const void* p) {
    u32 a;
    asm("{ .reg .u64 t; cvta.to.shared.u64 t, %1; cvt.u32.u64 %0, t; }"
        : "=r"(a) : "l"(p));
    return a;
}

__device__ __forceinline__ void ldsm4(u32& r0, u32& r1, u32& r2, u32& r3, u32 a) {
    asm volatile("ldmatrix.sync.aligned.m8n8.x4.shared.b16 {%0,%1,%2,%3},[%4];"
                 : "=r"(r0), "=r"(r1), "=r"(r2), "=r"(r3) : "r"(a));
}

__device__ __forceinline__ void cp16(u32 dst, const void* src) {
    asm volatile("cp.async.cg.shared.global [%0],[%1],16;" :: "r"(dst), "l"(src));
}

__device__ __forceinline__ void mma16816(float* d, const u32* a, const u32* b) {
    asm volatile(
        "mma.sync.aligned.m16n8k16.row.col.f32.bf16.bf16.f32 "
        "{%0,%1,%2,%3},{%4,%5,%6,%7},{%8,%9},{%0,%1,%2,%3};"
        : "+f"(d[0]), "+f"(d[1]), "+f"(d[2]), "+f"(d[3])
        : "r"(a[0]), "r"(a[1]), "r"(a[2]), "r"(a[3]), "r"(b[0]), "r"(b[1]));
}

__device__ __forceinline__ u32 packbf2(float lo, float hi) {
    __nv_bfloat162 t = __floats2bfloat162_rn(lo, hi);
    return *(u32*)&t;
}

// ---------------------------------------------------------------------------
// Kernel 0: weights fp32 -> bf16 (q rows pre-scaled); q bias scaled
// ---------------------------------------------------------------------------
__global__ void convert_weights(const float* __restrict__ qw,
                                const float* __restrict__ qb,
                                const float* __restrict__ pw,
                                const float* __restrict__ w1,
                                const float* __restrict__ w2) {
    const float scale = 0.17677669529663687f;
    int i = blockIdx.x * 256 + threadIdx.x;
    if (i < QKVC * CCH) {
        float v = qw[i];
        if (i < CCH * CCH) v *= scale;
        g_wq[i] = __float2bfloat16(v);
    }
    if (i < CCH * CCH)  g_wp[i] = __float2bfloat16(pw[i]);
    if (i < HIDD * CCH) g_w1[i] = __float2bfloat16(w1[i]);
    if (i < CCH * HIDD) g_w2[i] = __float2bfloat16(w2[i]);
    if (i < QKVC) g_qbias[i] = qb[i] * (i < CCH ? scale : 1.0f);
}

// ---------------------------------------------------------------------------
// Kernel 0b: per-(window,head) bias+mask value table (fp32)
// ---------------------------------------------------------------------------
__global__ void build_vt_kernel(const float* __restrict__ bias_table) {
    int win = blockIdx.x, h = blockIdx.y;
    float* dst = g_vt + ((size_t)(win * NHEAD) + h) * 4096;
    for (int e = threadIdx.x; e < 4096; e += 256) {
        int i = e >> 6, j = e & 63;
        float v;
        if (j >= NTOK) {
            v = -1e30f;
        } else {
            int ii = i < NTOK ? i : 0;
            int idx = (ii / 7 - j / 7 + 6) * 13 + (ii % 7 - j % 7 + 6);
            float b = bias_table[idx * NHEAD + h];
            int hi2 = (win >> 3) * WSZ + ii / 7, wi2 = (win & 7) * WSZ + ii % 7;
            int hj2 = (win >> 3) * WSZ + j / 7,  wj2 = (win & 7) * WSZ + j % 7;
            int ra = (hi2 < 49 ? 0 : (hi2 < 53 ? 1 : 2)) * 3 + (wi2 < 49 ? 0 : (wi2 < 53 ? 1 : 2));
            int rb = (hj2 < 49 ? 0 : (hj2 < 53 ? 1 : 2)) * 3 + (wj2 < 49 ? 0 : (wj2 < 53 ? 1 : 2));
            v = b + (ra != rb ? -100.0f : 0.0f);
        }
        dst[e] = v;
    }
}

// ---------------------------------------------------------------------------
// Kernel 1: LN1 + cyclic shift + window partition -> bf16. One warp per token.
// ---------------------------------------------------------------------------
__global__ void ln_shift_gather_kernel(const float* __restrict__ x,
                                       const float* __restrict__ g1,
                                       const float* __restrict__ b1) {
    int m = (blockIdx.x * blockDim.x + threadIdx.x) >> 5;
    int lane = threadIdx.x & 31;
    if (m >= MTOK) return;

    int wb  = m / NTOK;
    int n   = m - wb * NTOK;
    int bi  = wb >> 6;
    int win = wb & 63;
    int hs = (win >> 3) * WSZ + n / WSZ;
    int ws = (win & 7)  * WSZ + n % WSZ;
    int hh = hs + 3; if (hh >= 56) hh -= 56;
    int ww = ws + 3; if (ww >= 56) ww -= 56;

    const float* src = x + ((size_t)bi * 3136 + hh * 56 + ww) * CCH;
    float v[6];
    float s = 0.f;
#pragma unroll
    for (int i = 0; i < 6; i++) { v[i] = src[lane + 32 * i]; s += v[i]; }
    s = warp_sum(s);
    float mu = s * (1.0f / CCH);
    float q = 0.f;
#pragma unroll
    for (int i = 0; i < 6; i++) { float d = v[i] - mu; q += d * d; }
    q = warp_sum(q);
    float rstd = rsqrtf(q * (1.0f / CCH) + 1e-5f);

    bf16* dst = g_ln1 + (size_t)m * CCH;
#pragma unroll
    for (int i = 0; i < 6; i++) {
        int c = lane + 32 * i;
        dst[c] = __float2bfloat16((v[i] - mu) * rstd * g1[c] + b1[c]);
    }
}

// ---------------------------------------------------------------------------
// bf16 tensor-core GEMM: BM=128 BN=96 BK=64, NS-stage cp.async pipeline.
// NS=2 -> 3 blocks/SM (R12 schedule); NS=3 -> 2 blocks/SM (R14 schedule).
// EPI: 0 bias->OutT, 1 bias+GELU->OutT, 2 bias+res(fp32)->OutT
// ---------------------------------------------------------------------------
template <int NS, int EPI, typename OutT>
__global__ __launch_bounds__(256, NS == 2 ? 3 : 2) void bf16_gemm_kernel(
        const bf16* __restrict__ A,
        const bf16* __restrict__ W,
        const float* __restrict__ bias,
        OutT* __restrict__ C,
        const float* __restrict__ res,
        int M, int N, int K) {
    const int BM = 128, BN = 96, BK = 64, LDA = 72;
    const int STAGE_H = (BM + BN) * LDA;
    extern __shared__ bf16 smem[];

    int t = threadIdx.x;
    int bm = blockIdx.y * BM, bn = blockIdx.x * BN;
    int warp = t >> 5, lane = t & 31;
    int wm = (warp & 3) * 32, wn = (warp >> 2) * 48;
    int qr = lane >> 2, qc = lane & 3;

    u32 sbase = smem_u32(smem);

    int arow = t >> 1, ahalf = t & 1;
    const bf16* Ag = A + (size_t)(bm + arow) * K + ahalf * 32;
    u32 adst = sbase + (arow * LDA + ahalf * 32) * 2;
    int brow = t >> 1, bhalf = t & 1;
    const bf16* Wg = W + (size_t)(bn + brow) * K + bhalf * 32;
    u32 bdst = sbase + ((BM + brow) * LDA + bhalf * 32) * 2;
    bool hasb = (t < 192);

    int l15 = lane & 15, lhi = lane >> 4;
    u32 aoff = ((wm + l15) * LDA + lhi * 8) * 2;
    int bl = (lane & 7) + ((lane & 16) ? 8 : 0);
    int bkc = (lane >> 3) & 1;
    u32 boff = ((BM + wn + bl) * LDA + bkc * 8) * 2;

    float acc[2][6][4];
#pragma unroll
    for (int i = 0; i < 2; i++)
#pragma unroll
        for (int j = 0; j < 6; j++)
#pragma unroll
            for (int e = 0; e < 4; e++) acc[i][j][e] = 0.f;

    const u32 STB = STAGE_H * 2;
    int nk = K / BK;

    if (NS == 2) {
        // R12 schedule: double buffer, wait_group 0
#pragma unroll
        for (int j = 0; j < 4; j++) cp16(adst + j * 16, Ag + j * 8);
        if (hasb) {
#pragma unroll
            for (int j = 0; j < 4; j++) cp16(bdst + j * 16, Wg + j * 8);
        }
        asm volatile("cp.async.commit_group;" ::: "memory");

        for (int i = 0; i < nk; i++) {
            asm volatile("cp.async.wait_group 0;" ::: "memory");
            __syncthreads();

            if (i + 1 < nk) {
                u32 so = (u32)((i + 1) & 1) * STB;
                int k0 = (i + 1) * BK;
#pragma unroll
                for (int j = 0; j < 4; j++) cp16(adst + so + j * 16, Ag + k0 + j * 8);
                if (hasb) {
#pragma unroll
                    for (int j = 0; j < 4; j++) cp16(bdst + so + j * 16, Wg + k0 + j * 8);
                }
                asm volatile("cp.async.commit_group;" ::: "memory");
            }

            u32 so = (u32)(i & 1) * STB;
#pragma unroll
            for (int kk = 0; kk < 4; kk++) {
                u32 kb = kk * 32;
                u32 am[2][4];
                ldsm4(am[0][0], am[0][1], am[0][2], am[0][3], sbase + so + aoff + kb);
                ldsm4(am[1][0], am[1][1], am[1][2], am[1][3],
                      sbase + so + aoff + 16 * LDA * 2 + kb);
                u32 b[6][2];
#pragma unroll
                for (int g = 0; g < 3; g++)
                    ldsm4(b[2 * g][0], b[2 * g][1], b[2 * g + 1][0], b[2 * g + 1][1],
                          sbase + so + boff + (u32)(g * 16 * LDA * 2) + kb);
#pragma unroll
                for (int mi = 0; mi < 2; mi++)
#pragma unroll
                    for (int ni = 0; ni < 6; ni++)
                        mma16816(acc[mi][ni], am[mi], b[ni]);
            }
        }
    } else {
        // R14 schedule: NS=3, wait_group 1, unconditional commit
#pragma unroll
        for (int p = 0; p < NS - 1; p++) {
            if (p < nk) {
                u32 so = (u32)p * STB;
                int k0 = p * BK;
#pragma unroll
                for (int j = 0; j < 4; j++) cp16(adst + so + j * 16, Ag + k0 + j * 8);
                if (hasb) {
#pragma unroll
                    for (int j = 0; j < 4; j++) cp16(bdst + so + j * 16, Wg + k0 + j * 8);
                }
            }
            asm volatile("cp.async.commit_group;" ::: "memory");
        }

        int buf = 0;
        for (int i = 0; i < nk; i++) {
            asm volatile("cp.async.wait_group 1;" ::: "memory");
            __syncthreads();

            int nx = i + NS - 1;
            if (nx < nk) {
                u32 so = (u32)(nx % NS) * STB;
                int k0 = nx * BK;
#pragma unroll
                for (int j = 0; j < 4; j++) cp16(adst + so + j * 16, Ag + k0 + j * 8);
                if (hasb) {
#pragma unroll
                    for (int j = 0; j < 4; j++) cp16(bdst + so + j * 16, Wg + k0 + j * 8);
                }
            }
            asm volatile("cp.async.commit_group;" ::: "memory");

            u32 so = (u32)buf * STB;
#pragma unroll
            for (int kk = 0; kk < 4; kk++) {
                u32 kb = kk * 32;
                u32 am[2][4];
                ldsm4(am[0][0], am[0][1], am[0][2], am[0][3], sbase + so + aoff + kb);
                ldsm4(am[1][0], am[1][1], am[1][2], am[1][3],
                      sbase + so + aoff + 16 * LDA * 2 + kb);
                u32 b[6][2];
#pragma unroll
                for (int g = 0; g < 3; g++)
                    ldsm4(b[2 * g][0], b[2 * g][1], b[2 * g + 1][0], b[2 * g + 1][1],
                          sbase + so + boff + (u32)(g * 16 * LDA * 2) + kb);
#pragma unroll
                for (int mi = 0; mi < 2; mi++)
#pragma unroll
                    for (int ni = 0; ni < 6; ni++)
                        mma16816(acc[mi][ni], am[mi], b[ni]);
            }
            buf = (buf + 1 < NS) ? buf + 1 : 0;
        }
        asm volatile("cp.async.wait_group 0;" ::: "memory");
    }

    // epilogue: packed pair stores
#pragma unroll
    for (int mi = 0; mi < 2; mi++) {
#pragma unroll
        for (int ni = 0; ni < 6; ni++) {
            int row = bm + wm + mi * 16 + qr;
            int col = bn + wn + ni * 8 + qc * 2;
            float b0 = bias[col], b1v = bias[col + 1];
#pragma unroll
            for (int rh = 0; rh < 2; rh++) {
                int r = row + rh * 8;
                float v0 = acc[mi][ni][rh * 2]     + b0;
                float v1 = acc[mi][ni][rh * 2 + 1] + b1v;
                if (EPI == 1) {
                    v0 = 0.5f * v0 * (1.0f + erff(v0 * 0.70710678118654752f));
                    v1 = 0.5f * v1 * (1.0f + erff(v1 * 0.70710678118654752f));
                }
                if (EPI == 2) {
                    float2 rv = *(const float2*)(res + (size_t)r * N + col);
                    v0 += rv.x; v1 += rv.y;
                }
                if (sizeof(OutT) == 2) {
                    *(u32*)((bf16*)C + (size_t)r * N + col) = packbf2(v0, v1);
                } else {
                    float2 tv; tv.x = v0; tv.y = v1;
                    *(float2*)((float*)C + (size_t)r * N + col) = tv;
                }
            }
        }
    }
}

// ---------------------------------------------------------------------------
// Kernel 3: mma attention with precomputed value table (R12, unchanged).
// ---------------------------------------------------------------------------
__global__ __launch_bounds__(64) void attn_mma_kernel() {
    __shared__ __align__(16) bf16 qs[2][64 * 40];
    __shared__ __align__(16) bf16 ks[2][64 * 40];
    __shared__ __align__(16) bf16 vts[2][32 * 72];

    int tid = threadIdx.x, w = tid >> 5, lane = tid & 31;
    int wb = blockIdx.x, win = wb & 63;
    int h = blockIdx.y * 2 + w;

    u32 sq = smem_u32(qs[w]);
    u32 sk = smem_u32(ks[w]);
    u32 sv = smem_u32(vts[w]);

    const bf16* qbase = g_qkv + (size_t)(wb * NTOK) * QKVC + h * HEADD;
    for (int u = lane; u < 196; u += 32) {
        int n = u >> 2, c = u & 3;
        cp16(sq + n * 80 + c * 16, qbase + (size_t)n * QKVC + c * 8);
        cp16(sk + n * 80 + c * 16, qbase + (size_t)n * QKVC + CCH + c * 8);
    }
    asm volatile("cp.async.commit_group;" ::: "memory");

    {
        u32* qz = (u32*)qs[w];
        u32* kz = (u32*)ks[w];
        for (int u = lane; u < 300; u += 32) {
            int idx = (NTOK + u / 20) * 20 + u % 20;
            qz[idx] = 0; kz[idx] = 0;
        }
        u32* vz = (u32*)vts[w];
        for (int u = lane; u < 1152; u += 32) vz[u] = 0;
    }

    {
        const bf16* vbase = qbase + 2 * CCH;
        for (int u = lane; u < 784; u += 32) {
            int j = u >> 4, dd = u & 15;
            u32 pv = *(const u32*)(vbase + (size_t)j * QKVC + 2 * dd);
            vts[w][(2 * dd) * 72 + j]     = ((bf16*)&pv)[0];
            vts[w][(2 * dd + 1) * 72 + j] = ((bf16*)&pv)[1];
        }
    }

    asm volatile("cp.async.wait_group 0;" ::: "memory");
    __syncthreads();

    int qr = lane >> 2, qc = lane & 3;
    int l15 = lane & 15, lhi = lane >> 4;
    u32 aoff = (u32)((l15 * 40 + lhi * 8) * 2);
    int blr = (lane & 7) + ((lane & 16) ? 8 : 0);
    int bkc = (lane >> 3) & 1;
    u32 bKoff = (u32)((blr * 40 + bkc * 8) * 2);
    u32 bVoff = (u32)((blr * 72 + bkc * 8) * 2);

    const float* vtp = g_vt + ((size_t)(win * NHEAD) + h) * 4096;
    bf16* opbase = g_att + (size_t)(wb * NTOK) * CCH + h * HEADD;

#pragma unroll
    for (int mh = 0; mh < 2; mh++) {
        int m0 = mh * 32;
        float acc[2][8][4];
#pragma unroll
        for (int a = 0; a < 2; a++)
#pragma unroll
            for (int b = 0; b < 8; b++)
#pragma unroll
                for (int e = 0; e < 4; e++) acc[a][b][e] = 0.f;

#pragma unroll
        for (int kk = 0; kk < 2; kk++) {
            u32 kb = kk * 32;
            u32 am[2][4];
            ldsm4(am[0][0], am[0][1], am[0][2], am[0][3], sq + aoff + (u32)(m0 * 80) + kb);
            ldsm4(am[1][0], am[1][1], am[1][2], am[1][3], sq + aoff + (u32)((m0 + 16) * 80) + kb);
            u32 b[8][2];
#pragma unroll
            for (int np = 0; np < 4; np++)
                ldsm4(b[2 * np][0], b[2 * np][1], b[2 * np + 1][0], b[2 * np + 1][1],
                      sk + bKoff + (u32)(np * 16 * 80) + kb);
#pragma unroll
            for (int mi = 0; mi < 2; mi++)
#pragma unroll
                for (int ni = 0; ni < 8; ni++)
                    mma16816(acc[mi][ni], am[mi], b[ni]);
        }

#pragma unroll
        for (int mi = 0; mi < 2; mi++)
#pragma unroll
            for (int ni = 0; ni < 8; ni++) {
                int c = ni * 8 + 2 * qc;
#pragma unroll
                for (int rh = 0; rh < 2; rh++) {
                    int r = m0 + mi * 16 + qr + rh * 8;
                    float2 bv = *(const float2*)(vtp + r * 64 + c);
                    acc[mi][ni][rh * 2]     += bv.x;
                    acc[mi][ni][rh * 2 + 1] += bv.y;
                }
            }

#pragma unroll
        for (int mi = 0; mi < 2; mi++)
#pragma unroll
            for (int rh = 0; rh < 2; rh++) {
                float mx = -1e30f;
#pragma unroll
                for (int ni = 0; ni < 8; ni++)
#pragma unroll
                    for (int el = 0; el < 2; el++)
                        mx = fmaxf(mx, acc[mi][ni][rh * 2 + el]);
                mx = fmaxf(mx, __shfl_xor_sync(0xffffffffu, mx, 1));
                mx = fmaxf(mx, __shfl_xor_sync(0xffffffffu, mx, 2));
                float sum = 0.f;
#pragma unroll
                for (int ni = 0; ni < 8; ni++)
#pragma unroll
                    for (int el = 0; el < 2; el++) {
                        float p = __expf(acc[mi][ni][rh * 2 + el] - mx);
                        acc[mi][ni][rh * 2 + el] = p;
                        sum += p;
                    }
                sum += __shfl_xor_sync(0xffffffffu, sum, 1);
                sum += __shfl_xor_sync(0xffffffffu, sum, 2);
                float inv = 1.0f / sum;
#pragma unroll
                for (int ni = 0; ni < 8; ni++)
#pragma unroll
                    for (int el = 0; el < 2; el++)
                        acc[mi][ni][rh * 2 + el] *= inv;
            }

        u32 pa[2][4][4];
#pragma unroll
        for (int mi = 0; mi < 2; mi++)
#pragma unroll
            for (int kt = 0; kt < 4; kt++) {
                pa[mi][kt][0] = packbf2(acc[mi][2 * kt][0],     acc[mi][2 * kt][1]);
                pa[mi][kt][1] = packbf2(acc[mi][2 * kt][2],     acc[mi][2 * kt][3]);
                pa[mi][kt][2] = packbf2(acc[mi][2 * kt + 1][0], acc[mi][2 * kt + 1][1]);
                pa[mi][kt][3] = packbf2(acc[mi][2 * kt + 1][2], acc[mi][2 * kt + 1][3]);
            }

        float o[2][4][4];
#pragma unroll
        for (int a = 0; a < 2; a++)
#pragma unroll
            for (int b = 0; b < 4; b++)
#pragma unroll
                for (int e = 0; e < 4; e++) o[a][b][e] = 0.f;
#pragma unroll
        for (int kt = 0; kt < 4; kt++) {
            u32 bv[4][2];
            ldsm4(bv[0][0], bv[0][1], bv[1][0], bv[1][1], sv + bVoff + (u32)(kt * 32));
            ldsm4(bv[2][0], bv[2][1], bv[3][0], bv[3][1],
                  sv + bVoff + (u32)(16 * 144) + (u32)(kt * 32));
#pragma unroll
            for (int mi = 0; mi < 2; mi++)
#pragma unroll
                for (int nv = 0; nv < 4; nv++)
                    mma16816(o[mi][nv], pa[mi][kt], bv[nv]);
        }

#pragma unroll
        for (int mi = 0; mi < 2; mi++)
#pragma unroll
            for (int rh = 0; rh < 2; rh++) {
                int r = m0 + mi * 16 + qr + rh * 8;
                if (r < NTOK) {
#pragma unroll
                    for (int nv = 0; nv < 4; nv++) {
                        u32 pk = packbf2(o[mi][nv][rh * 2], o[mi][nv][rh * 2 + 1]);
                        *(u32*)(opbase + (size_t)r * CCH + nv * 8 + 2 * qc) = pk;
                    }
                }
            }
    }
}

// ---------------------------------------------------------------------------
// Kernel 4: window reverse + unshift + residual + LN2. (proj bf16)
// ---------------------------------------------------------------------------
__global__ void reverse_add_ln2_kernel(const float* __restrict__ x,
                                       const float* __restrict__ g2,
                                       const float* __restrict__ b2) {
    int m = (blockIdx.x * blockDim.x + threadIdx.x) >> 5;
    int lane = threadIdx.x & 31;
    if (m >= MTOK) return;

    int wb  = m / NTOK;
    int n   = m - wb * NTOK;
    int bi  = wb >> 6;
    int win = wb & 63;
    int hs = (win >> 3) * WSZ + n / WSZ;
    int ws = (win & 7)  * WSZ + n % WSZ;
    int hh = hs + 3; if (hh >= 56) hh -= 56;
    int ww = ws + 3; if (ww >= 56) ww -= 56;
    size_t tt = (size_t)bi * 3136 + hh * 56 + ww;

    const float* xs = x + tt * CCH;
    const bf16* pr = g_proj + (size_t)m * CCH;
    float* x2 = g_x2 + tt * CCH;
    bf16* hl  = g_ln2 + tt * CCH;

    float v[6];
    float s = 0.f;
#pragma unroll
    for (int i = 0; i < 6; i++) {
        int c = lane + 32 * i;
        v[i] = xs[c] + __bfloat162float(pr[c]);
        x2[c] = v[i];
        s += v[i];
    }
    s = warp_sum(s);
    float mu = s * (1.0f / CCH);
    float q = 0.f;
#pragma unroll
    for (int i = 0; i < 6; i++) { float d = v[i] - mu; q += d * d; }
    q = warp_sum(q);
    float rstd = rsqrtf(q * (1.0f / CCH) + 1e-5f);
#pragma unroll
    for (int i = 0; i < 6; i++) {
        int c = lane + 32 * i;
        hl[c] = __float2bfloat16((v[i] - mu) * rstd * g2[c] + b2[c]);
    }
}

// ---------------------------------------------------------------------------
// Host launcher
// ---------------------------------------------------------------------------
extern "C" void kernel_launch(void* const* d_in, const int* in_sizes, int n_in,
                              void* d_out, int out_size) {
    const float* x          = (const float*)d_in[0];
    const float* g1         = (const float*)d_in[1];
    const float* b1         = (const float*)d_in[2];
    const float* qkv_w      = (const float*)d_in[3];
    const float* qkv_b      = (const float*)d_in[4];
    const float* proj_w     = (const float*)d_in[5];
    const float* proj_b     = (const float*)d_in[6];
    const float* bias_table = (const float*)d_in[7];
    const float* g2         = (const float*)d_in[8];
    const float* b2         = (const float*)d_in[9];
    const float* fc1_w      = (const float*)d_in[10];
    const float* fc1_b      = (const float*)d_in[11];
    const float* fc2_w      = (const float*)d_in[12];
    const float* fc2_b      = (const float*)d_in[13];
    float* out = (float*)d_out;

    bf16 *p_ln1, *p_qkvb, *p_att, *p_proj, *p_ln2, *p_hid, *p_wq, *p_wp, *p_w1, *p_w2;
    float *p_x2, *p_qbias;
    cudaGetSymbolAddress((void**)&p_ln1,  g_ln1);
    cudaGetSymbolAddress((void**)&p_qkvb, g_qkv);
    cudaGetSymbolAddress((void**)&p_att,  g_att);
    cudaGetSymbolAddress((void**)&p_proj, g_proj);
    cudaGetSymbolAddress((void**)&p_x2,   g_x2);
    cudaGetSymbolAddress((void**)&p_ln2,  g_ln2);
    cudaGetSymbolAddress((void**)&p_hid,  g_hid);
    cudaGetSymbolAddress((void**)&p_wq,   g_wq);
    cudaGetSymbolAddress((void**)&p_wp,   g_wp);
    cudaGetSymbolAddress((void**)&p_w1,   g_w1);
    cudaGetSymbolAddress((void**)&p_w2,   g_w2);
    cudaGetSymbolAddress((void**)&p_qbias, g_qbias);

    const int SMEM2 = 2 * (128 + 96) * 72 * 2;   // 64512 bytes
    const int SMEM3 = 3 * (128 + 96) * 72 * 2;   // 96768 bytes
    cudaFuncSetAttribute(bf16_gemm_kernel<3, 0, bf16>,
                         cudaFuncAttributeMaxDynamicSharedMemorySize, SMEM3);
    cudaFuncSetAttribute(bf16_gemm_kernel<2, 0, bf16>,
                         cudaFuncAttributeMaxDynamicSharedMemorySize, SMEM2);
    cudaFuncSetAttribute(bf16_gemm_kernel<2, 1, bf16>,
                         cudaFuncAttributeMaxDynamicSharedMemorySize, SMEM2);
    cudaFuncSetAttribute(bf16_gemm_kernel<2, 2, float>,
                         cudaFuncAttributeMaxDynamicSharedMemorySize, SMEM2);

    convert_weights<<<576, 256>>>(qkv_w, qkv_b, proj_w, fc1_w, fc2_w);
    build_vt_kernel<<<dim3(64, NHEAD), 256>>>(bias_table);

    ln_shift_gather_kernel<<<MTOK / 8, 256>>>(x, g1, b1);

    // qkv: nk=3 -> NS=3 (measured -6.5us vs NS=2)
    bf16_gemm_kernel<3, 0, bf16><<<dim3(QKVC / 96, MTOK / 128), 256, SMEM3>>>(
        p_ln1, p_wq, p_qbias, p_qkvb, nullptr, MTOK, QKVC, CCH);

    attn_mma_kernel<<<dim3(MTOK / NTOK, NHEAD / 2), 64>>>();

    // proj: NS=2 (R12 config)
    bf16_gemm_kernel<2, 0, bf16><<<dim3(CCH / 96, MTOK / 128), 256, SMEM2>>>(
        p_att, p_wp, proj_b, p_proj, nullptr, MTOK, CCH, CCH);

    reverse_add_ln2_kernel<<<MTOK / 8, 256>>>(x, g2, b2);

    // fc1: NS=2 (R12 config — NS=3 measured slower)
    bf16_gemm_kernel<2, 1, bf16><<<dim3(HIDD / 96, MTOK / 128), 256, SMEM2>>>(
        p_ln2, p_w1, fc1_b, p_hid, nullptr, MTOK, HIDD, CCH);

    // fc2: NS=2 (R12 config — NS=3 measured slower)
    bf16_gemm_kernel<2, 2, float><<<dim3(CCH / 96, MTOK / 128), 256, SMEM2>>>(
        p_hid, p_w2, fc2_b, out, p_x2, MTOK, CCH, HIDD);
}

// round 17
// speedup vs baseline: 1.0352x; 1.0085x over previous
#include <cuda_runtime.h>
#include <cuda_bf16.h>
#include <cstdint>
#include <math.h>

// ---------------------------------------------------------------------------
// Swin block, Round 17: R16 base + (a) fc2 NS=3, (b) float2 LN kernels,
// (c) attention QK^T/softmax trimmed to 7 n-frags.
// ---------------------------------------------------------------------------

#define MTOK   100352
#define CCH    192
#define NHEAD  6
#define HEADD  32
#define WSZ    7
#define NTOK   49
#define HIDD   768
#define QKVC   576

typedef __nv_bfloat16 bf16;
typedef unsigned int u32;
typedef unsigned short u16;

// Scratch
__device__ bf16  g_ln1 [MTOK * CCH];
__device__ bf16  g_qkv [MTOK * QKVC];
__device__ bf16  g_att [MTOK * CCH];
__device__ bf16  g_proj[MTOK * CCH];
__device__ float g_x2  [MTOK * CCH];
__device__ bf16  g_ln2 [MTOK * CCH];
__device__ bf16  g_hid [MTOK * HIDD];
__device__ bf16  g_wq  [QKVC * CCH];
__device__ bf16  g_wp  [CCH * CCH];
__device__ bf16  g_w1  [HIDD * CCH];
__device__ bf16  g_w2  [CCH * HIDD];
__device__ float g_qbias[QKVC];
__device__ float g_vt  [64 * NHEAD * 4096];

__device__ __forceinline__ float warp_sum(float v) {
#pragma unroll
    for (int o = 16; o; o >>= 1) v += __shfl_xor_sync(0xffffffffu, v, o);
    return v;
}

__device__ __forceinline__ u32 smem_u32(const void* p) {
    u32 a;
    asm("{ .reg .u64 t; cvta.to.shared.u64 t, %1; cvt.u32.u64 %0, t; }"
        : "=r"(a) : "l"(p));
    return a;
}

__device__ __forceinline__ void ldsm4(u32& r0, u32& r1, u32& r2, u32& r3, u32 a) {
    asm volatile("ldmatrix.sync.aligned.m8n8.x4.shared.b16 {%0,%1,%2,%3},[%4];"
                 : "=r"(r0), "=r"(r1), "=r"(r2), "=r"(r3) : "r"(a));
}

__device__ __forceinline__ void cp16(u32 dst, const void* src) {
    asm volatile("cp.async.cg.shared.global [%0],[%1],16;" :: "r"(dst), "l"(src));
}

__device__ __forceinline__ void mma16816(float* d, const u32* a, const u32* b) {
    asm volatile(
        "mma.sync.aligned.m16n8k16.row.col.f32.bf16.bf16.f32 "
        "{%0,%1,%2,%3},{%4,%5,%6,%7},{%8,%9},{%0,%1,%2,%3};"
        : "+f"(d[0]), "+f"(d[1]), "+f"(d[2]), "+f"(d[3])
        : "r"(a[0]), "r"(a[1]), "r"(a[2]), "r"(a[3]), "r"(b[0]), "r"(b[1]));
}

__device__ __forceinline__ u32 packbf2(float lo, float hi) {
    __nv_bfloat162 t = __floats2bfloat162_rn(lo, hi);
    return *(u32*)&t;
}

// ---------------------------------------------------------------------------
// Kernel 0: weights fp32 -> bf16 (q rows pre-scaled); q bias scaled
// ---------------------------------------------------------------------------
__global__ void convert_weights(const float* __restrict__ qw,
                                const float* __restrict__ qb,
                                const float* __restrict__ pw,
                                const float* __restrict__ w1,
                                const float* __restrict__ w2) {
    const float scale = 0.17677669529663687f;
    int i = blockIdx.x * 256 + threadIdx.x;
    if (i < QKVC * CCH) {
        float v = qw[i];
        if (i < CCH * CCH) v *= scale;
        g_wq[i] = __float2bfloat16(v);
    }
    if (i < CCH * CCH)  g_wp[i] = __float2bfloat16(pw[i]);
    if (i < HIDD * CCH) g_w1[i] = __float2bfloat16(w1[i]);
    if (i < CCH * HIDD) g_w2[i] = __float2bfloat16(w2[i]);
    if (i < QKVC) g_qbias[i] = qb[i] * (i < CCH ? scale : 1.0f);
}

// ---------------------------------------------------------------------------
// Kernel 0b: per-(window,head) bias+mask value table (fp32)
// ---------------------------------------------------------------------------
__global__ void build_vt_kernel(const float* __restrict__ bias_table) {
    int win = blockIdx.x, h = blockIdx.y;
    float* dst = g_vt + ((size_t)(win * NHEAD) + h) * 4096;
    for (int e = threadIdx.x; e < 4096; e += 256) {
        int i = e >> 6, j = e & 63;
        float v;
        if (j >= NTOK) {
            v = -1e30f;
        } else {
            int ii = i < NTOK ? i : 0;
            int idx = (ii / 7 - j / 7 + 6) * 13 + (ii % 7 - j % 7 + 6);
            float b = bias_table[idx * NHEAD + h];
            int hi2 = (win >> 3) * WSZ + ii / 7, wi2 = (win & 7) * WSZ + ii % 7;
            int hj2 = (win >> 3) * WSZ + j / 7,  wj2 = (win & 7) * WSZ + j % 7;
            int ra = (hi2 < 49 ? 0 : (hi2 < 53 ? 1 : 2)) * 3 + (wi2 < 49 ? 0 : (wi2 < 53 ? 1 : 2));
            int rb = (hj2 < 49 ? 0 : (hj2 < 53 ? 1 : 2)) * 3 + (wj2 < 49 ? 0 : (wj2 < 53 ? 1 : 2));
            v = b + (ra != rb ? -100.0f : 0.0f);
        }
        dst[e] = v;
    }
}

// ---------------------------------------------------------------------------
// Kernel 1: LN1 + cyclic shift + window partition -> bf16. One warp per token.
// float2-vectorized loads/stores.
// ---------------------------------------------------------------------------
__global__ void ln_shift_gather_kernel(const float* __restrict__ x,
                                       const float* __restrict__ g1,
                                       const float* __restrict__ b1) {
    int m = (blockIdx.x * blockDim.x + threadIdx.x) >> 5;
    int lane = threadIdx.x & 31;
    if (m >= MTOK) return;

    int wb  = m / NTOK;
    int n   = m - wb * NTOK;
    int bi  = wb >> 6;
    int win = wb & 63;
    int hs = (win >> 3) * WSZ + n / WSZ;
    int ws = (win & 7)  * WSZ + n % WSZ;
    int hh = hs + 3; if (hh >= 56) hh -= 56;
    int ww = ws + 3; if (ww >= 56) ww -= 56;

    const float2* src = (const float2*)(x + ((size_t)bi * 3136 + hh * 56 + ww) * CCH);
    float2 v[3];
    float s = 0.f;
#pragma unroll
    for (int i = 0; i < 3; i++) {
        v[i] = src[lane + 32 * i];
        s += v[i].x + v[i].y;
    }
    s = warp_sum(s);
    float mu = s * (1.0f / CCH);
    float q = 0.f;
#pragma unroll
    for (int i = 0; i < 3; i++) {
        float dx = v[i].x - mu, dy = v[i].y - mu;
        q += dx * dx + dy * dy;
    }
    q = warp_sum(q);
    float rstd = rsqrtf(q * (1.0f / CCH) + 1e-5f);

    u32* dst = (u32*)(g_ln1 + (size_t)m * CCH);
    const float2* g1v = (const float2*)g1;
    const float2* b1v = (const float2*)b1;
#pragma unroll
    for (int i = 0; i < 3; i++) {
        int c2 = lane + 32 * i;
        float2 gg = g1v[c2], bb = b1v[c2];
        dst[c2] = packbf2((v[i].x - mu) * rstd * gg.x + bb.x,
                          (v[i].y - mu) * rstd * gg.y + bb.y);
    }
}

// ---------------------------------------------------------------------------
// bf16 tensor-core GEMM: BM=128 BN=96 BK=64, NS-stage cp.async pipeline.
// NS=2 -> 3 blocks/SM (R12 schedule); NS=3 -> 2 blocks/SM (R14 schedule).
// EPI: 0 bias->OutT, 1 bias+GELU->OutT, 2 bias+res(fp32)->OutT
// ---------------------------------------------------------------------------
template <int NS, int EPI, typename OutT>
__global__ __launch_bounds__(256, NS == 2 ? 3 : 2) void bf16_gemm_kernel(
        const bf16* __restrict__ A,
        const bf16* __restrict__ W,
        const float* __restrict__ bias,
        OutT* __restrict__ C,
        const float* __restrict__ res,
        int M, int N, int K) {
    const int BM = 128, BN = 96, BK = 64, LDA = 72;
    const int STAGE_H = (BM + BN) * LDA;
    extern __shared__ bf16 smem[];

    int t = threadIdx.x;
    int bm = blockIdx.y * BM, bn = blockIdx.x * BN;
    int warp = t >> 5, lane = t & 31;
    int wm = (warp & 3) * 32, wn = (warp >> 2) * 48;
    int qr = lane >> 2, qc = lane & 3;

    u32 sbase = smem_u32(smem);

    int arow = t >> 1, ahalf = t & 1;
    const bf16* Ag = A + (size_t)(bm + arow) * K + ahalf * 32;
    u32 adst = sbase + (arow * LDA + ahalf * 32) * 2;
    int brow = t >> 1, bhalf = t & 1;
    const bf16* Wg = W + (size_t)(bn + brow) * K + bhalf * 32;
    u32 bdst = sbase + ((BM + brow) * LDA + bhalf * 32) * 2;
    bool hasb = (t < 192);

    int l15 = lane & 15, lhi = lane >> 4;
    u32 aoff = ((wm + l15) * LDA + lhi * 8) * 2;
    int bl = (lane & 7) + ((lane & 16) ? 8 : 0);
    int bkc = (lane >> 3) & 1;
    u32 boff = ((BM + wn + bl) * LDA + bkc * 8) * 2;

    float acc[2][6][4];
#pragma unroll
    for (int i = 0; i < 2; i++)
#pragma unroll
        for (int j = 0; j < 6; j++)
#pragma unroll
            for (int e = 0; e < 4; e++) acc[i][j][e] = 0.f;

    const u32 STB = STAGE_H * 2;
    int nk = K / BK;

    if (NS == 2) {
#pragma unroll
        for (int j = 0; j < 4; j++) cp16(adst + j * 16, Ag + j * 8);
        if (hasb) {
#pragma unroll
            for (int j = 0; j < 4; j++) cp16(bdst + j * 16, Wg + j * 8);
        }
        asm volatile("cp.async.commit_group;" ::: "memory");

        for (int i = 0; i < nk; i++) {
            asm volatile("cp.async.wait_group 0;" ::: "memory");
            __syncthreads();

            if (i + 1 < nk) {
                u32 so = (u32)((i + 1) & 1) * STB;
                int k0 = (i + 1) * BK;
#pragma unroll
                for (int j = 0; j < 4; j++) cp16(adst + so + j * 16, Ag + k0 + j * 8);
                if (hasb) {
#pragma unroll
                    for (int j = 0; j < 4; j++) cp16(bdst + so + j * 16, Wg + k0 + j * 8);
                }
                asm volatile("cp.async.commit_group;" ::: "memory");
            }

            u32 so = (u32)(i & 1) * STB;
#pragma unroll
            for (int kk = 0; kk < 4; kk++) {
                u32 kb = kk * 32;
                u32 am[2][4];
                ldsm4(am[0][0], am[0][1], am[0][2], am[0][3], sbase + so + aoff + kb);
                ldsm4(am[1][0], am[1][1], am[1][2], am[1][3],
                      sbase + so + aoff + 16 * LDA * 2 + kb);
                u32 b[6][2];
#pragma unroll
                for (int g = 0; g < 3; g++)
                    ldsm4(b[2 * g][0], b[2 * g][1], b[2 * g + 1][0], b[2 * g + 1][1],
                          sbase + so + boff + (u32)(g * 16 * LDA * 2) + kb);
#pragma unroll
                for (int mi = 0; mi < 2; mi++)
#pragma unroll
                    for (int ni = 0; ni < 6; ni++)
                        mma16816(acc[mi][ni], am[mi], b[ni]);
            }
        }
    } else {
#pragma unroll
        for (int p = 0; p < NS - 1; p++) {
            if (p < nk) {
                u32 so = (u32)p * STB;
                int k0 = p * BK;
#pragma unroll
                for (int j = 0; j < 4; j++) cp16(adst + so + j * 16, Ag + k0 + j * 8);
                if (hasb) {
#pragma unroll
                    for (int j = 0; j < 4; j++) cp16(bdst + so + j * 16, Wg + k0 + j * 8);
                }
            }
            asm volatile("cp.async.commit_group;" ::: "memory");
        }

        int buf = 0;
        for (int i = 0; i < nk; i++) {
            asm volatile("cp.async.wait_group 1;" ::: "memory");
            __syncthreads();

            int nx = i + NS - 1;
            if (nx < nk) {
                u32 so = (u32)(nx % NS) * STB;
                int k0 = nx * BK;
#pragma unroll
                for (int j = 0; j < 4; j++) cp16(adst + so + j * 16, Ag + k0 + j * 8);
                if (hasb) {
#pragma unroll
                    for (int j = 0; j < 4; j++) cp16(bdst + so + j * 16, Wg + k0 + j * 8);
                }
            }
            asm volatile("cp.async.commit_group;" ::: "memory");

            u32 so = (u32)buf * STB;
#pragma unroll
            for (int kk = 0; kk < 4; kk++) {
                u32 kb = kk * 32;
                u32 am[2][4];
                ldsm4(am[0][0], am[0][1], am[0][2], am[0][3], sbase + so + aoff + kb);
                ldsm4(am[1][0], am[1][1], am[1][2], am[1][3],
                      sbase + so + aoff + 16 * LDA * 2 + kb);
                u32 b[6][2];
#pragma unroll
                for (int g = 0; g < 3; g++)
                    ldsm4(b[2 * g][0], b[2 * g][1], b[2 * g + 1][0], b[2 * g + 1][1],
                          sbase + so + boff + (u32)(g * 16 * LDA * 2) + kb);
#pragma unroll
                for (int mi = 0; mi < 2; mi++)
#pragma unroll
                    for (int ni = 0; ni < 6; ni++)
                        mma16816(acc[mi][ni], am[mi], b[ni]);
            }
            buf = (buf + 1 < NS) ? buf + 1 : 0;
        }
        asm volatile("cp.async.wait_group 0;" ::: "memory");
    }

    // epilogue: packed pair stores
#pragma unroll
    for (int mi = 0; mi < 2; mi++) {
#pragma unroll
        for (int ni = 0; ni < 6; ni++) {
            int row = bm + wm + mi * 16 + qr;
            int col = bn + wn + ni * 8 + qc * 2;
            float b0 = bias[col], b1v = bias[col + 1];
#pragma unroll
            for (int rh = 0; rh < 2; rh++) {
                int r = row + rh * 8;
                float v0 = acc[mi][ni][rh * 2]     + b0;
                float v1 = acc[mi][ni][rh * 2 + 1] + b1v;
                if (EPI == 1) {
                    v0 = 0.5f * v0 * (1.0f + erff(v0 * 0.70710678118654752f));
                    v1 = 0.5f * v1 * (1.0f + erff(v1 * 0.70710678118654752f));
                }
                if (EPI == 2) {
                    float2 rv = *(const float2*)(res + (size_t)r * N + col);
                    v0 += rv.x; v1 += rv.y;
                }
                if (sizeof(OutT) == 2) {
                    *(u32*)((bf16*)C + (size_t)r * N + col) = packbf2(v0, v1);
                } else {
                    float2 tv; tv.x = v0; tv.y = v1;
                    *(float2*)((float*)C + (size_t)r * N + col) = tv;
                }
            }
        }
    }
}

// ---------------------------------------------------------------------------
// Kernel 3: mma attention with value table; QK^T/softmax over 7 n-frags
// (cols 56-63 are pad: P stays exactly 0 from init, V rows zeroed).
// ---------------------------------------------------------------------------
__global__ __launch_bounds__(64) void attn_mma_kernel() {
    __shared__ __align__(16) bf16 qs[2][64 * 40];
    __shared__ __align__(16) bf16 ks[2][64 * 40];
    __shared__ __align__(16) bf16 vts[2][32 * 72];

    int tid = threadIdx.x, w = tid >> 5, lane = tid & 31;
    int wb = blockIdx.x, win = wb & 63;
    int h = blockIdx.y * 2 + w;

    u32 sq = smem_u32(qs[w]);
    u32 sk = smem_u32(ks[w]);
    u32 sv = smem_u32(vts[w]);

    const bf16* qbase = g_qkv + (size_t)(wb * NTOK) * QKVC + h * HEADD;
    for (int u = lane; u < 196; u += 32) {
        int n = u >> 2, c = u & 3;
        cp16(sq + n * 80 + c * 16, qbase + (size_t)n * QKVC + c * 8);
        cp16(sk + n * 80 + c * 16, qbase + (size_t)n * QKVC + CCH + c * 8);
    }
    asm volatile("cp.async.commit_group;" ::: "memory");

    {
        u32* qz = (u32*)qs[w];
        u32* kz = (u32*)ks[w];
        for (int u = lane; u < 300; u += 32) {
            int idx = (NTOK + u / 20) * 20 + u % 20;
            qz[idx] = 0; kz[idx] = 0;
        }
        u32* vz = (u32*)vts[w];
        for (int u = lane; u < 1152; u += 32) vz[u] = 0;
    }

    {
        const bf16* vbase = qbase + 2 * CCH;
        for (int u = lane; u < 784; u += 32) {
            int j = u >> 4, dd = u & 15;
            u32 pv = *(const u32*)(vbase + (size_t)j * QKVC + 2 * dd);
            vts[w][(2 * dd) * 72 + j]     = ((bf16*)&pv)[0];
            vts[w][(2 * dd + 1) * 72 + j] = ((bf16*)&pv)[1];
        }
    }

    asm volatile("cp.async.wait_group 0;" ::: "memory");
    __syncthreads();

    int qr = lane >> 2, qc = lane & 3;
    int l15 = lane & 15, lhi = lane >> 4;
    u32 aoff = (u32)((l15 * 40 + lhi * 8) * 2);
    int blr = (lane & 7) + ((lane & 16) ? 8 : 0);
    int bkc = (lane >> 3) & 1;
    u32 bKoff = (u32)((blr * 40 + bkc * 8) * 2);
    u32 bVoff = (u32)((blr * 72 + bkc * 8) * 2);

    const float* vtp = g_vt + ((size_t)(win * NHEAD) + h) * 4096;
    bf16* opbase = g_att + (size_t)(wb * NTOK) * CCH + h * HEADD;

#pragma unroll
    for (int mh = 0; mh < 2; mh++) {
        int m0 = mh * 32;
        float acc[2][8][4];
#pragma unroll
        for (int a = 0; a < 2; a++)
#pragma unroll
            for (int b = 0; b < 8; b++)
#pragma unroll
                for (int e = 0; e < 4; e++) acc[a][b][e] = 0.f;

        // ---- QK^T over 7 n-frags (cols 0-55; 56-63 stay zero) ----
#pragma unroll
        for (int kk = 0; kk < 2; kk++) {
            u32 kb = kk * 32;
            u32 am[2][4];
            ldsm4(am[0][0], am[0][1], am[0][2], am[0][3], sq + aoff + (u32)(m0 * 80) + kb);
            ldsm4(am[1][0], am[1][1], am[1][2], am[1][3], sq + aoff + (u32)((m0 + 16) * 80) + kb);
            u32 b[8][2];
#pragma unroll
            for (int np = 0; np < 4; np++)
                ldsm4(b[2 * np][0], b[2 * np][1], b[2 * np + 1][0], b[2 * np + 1][1],
                      sk + bKoff + (u32)(np * 16 * 80) + kb);
#pragma unroll
            for (int mi = 0; mi < 2; mi++)
#pragma unroll
                for (int ni = 0; ni < 7; ni++)
                    mma16816(acc[mi][ni], am[mi], b[ni]);
        }

        // ---- add precomputed bias+mask values (cols 0-55) ----
#pragma unroll
        for (int mi = 0; mi < 2; mi++)
#pragma unroll
            for (int ni = 0; ni < 7; ni++) {
                int c = ni * 8 + 2 * qc;
#pragma unroll
                for (int rh = 0; rh < 2; rh++) {
                    int r = m0 + mi * 16 + qr + rh * 8;
                    float2 bv = *(const float2*)(vtp + r * 64 + c);
                    acc[mi][ni][rh * 2]     += bv.x;
                    acc[mi][ni][rh * 2 + 1] += bv.y;
                }
            }

        // ---- softmax over ni<7 (pads get exp->0 via vt; ni=7 stays 0) ----
#pragma unroll
        for (int mi = 0; mi < 2; mi++)
#pragma unroll
            for (int rh = 0; rh < 2; rh++) {
                float mx = -1e30f;
#pragma unroll
                for (int ni = 0; ni < 7; ni++)
#pragma unroll
                    for (int el = 0; el < 2; el++)
                        mx = fmaxf(mx, acc[mi][ni][rh * 2 + el]);
                mx = fmaxf(mx, __shfl_xor_sync(0xffffffffu, mx, 1));
                mx = fmaxf(mx, __shfl_xor_sync(0xffffffffu, mx, 2));
                float sum = 0.f;
#pragma unroll
                for (int ni = 0; ni < 7; ni++)
#pragma unroll
                    for (int el = 0; el < 2; el++) {
                        float p = __expf(acc[mi][ni][rh * 2 + el] - mx);
                        acc[mi][ni][rh * 2 + el] = p;
                        sum += p;
                    }
                sum += __shfl_xor_sync(0xffffffffu, sum, 1);
                sum += __shfl_xor_sync(0xffffffffu, sum, 2);
                float inv = 1.0f / sum;
#pragma unroll
                for (int ni = 0; ni < 7; ni++)
#pragma unroll
                    for (int el = 0; el < 2; el++)
                        acc[mi][ni][rh * 2 + el] *= inv;
            }

        // ---- pack P into A fragments (acc[..][7] == 0 -> P cols 56-63 zero) ----
        u32 pa[2][4][4];
#pragma unroll
        for (int mi = 0; mi < 2; mi++)
#pragma unroll
            for (int kt = 0; kt < 4; kt++) {
                pa[mi][kt][0] = packbf2(acc[mi][2 * kt][0],     acc[mi][2 * kt][1]);
                pa[mi][kt][1] = packbf2(acc[mi][2 * kt][2],     acc[mi][2 * kt][3]);
                pa[mi][kt][2] = packbf2(acc[mi][2 * kt + 1][0], acc[mi][2 * kt + 1][1]);
                pa[mi][kt][3] = packbf2(acc[mi][2 * kt + 1][2], acc[mi][2 * kt + 1][3]);
            }

        // ---- P @ V ----
        float o[2][4][4];
#pragma unroll
        for (int a = 0; a < 2; a++)
#pragma unroll
            for (int b = 0; b < 4; b++)
#pragma unroll
                for (int e = 0; e < 4; e++) o[a][b][e] = 0.f;
#pragma unroll
        for (int kt = 0; kt < 4; kt++) {
            u32 bv[4][2];
            ldsm4(bv[0][0], bv[0][1], bv[1][0], bv[1][1], sv + bVoff + (u32)(kt * 32));
            ldsm4(bv[2][0], bv[2][1], bv[3][0], bv[3][1],
                  sv + bVoff + (u32)(16 * 144) + (u32)(kt * 32));
#pragma unroll
            for (int mi = 0; mi < 2; mi++)
#pragma unroll
                for (int nv = 0; nv < 4; nv++)
                    mma16816(o[mi][nv], pa[mi][kt], bv[nv]);
        }

        // ---- store ----
#pragma unroll
        for (int mi = 0; mi < 2; mi++)
#pragma unroll
            for (int rh = 0; rh < 2; rh++) {
                int r = m0 + mi * 16 + qr + rh * 8;
                if (r < NTOK) {
#pragma unroll
                    for (int nv = 0; nv < 4; nv++) {
                        u32 pk = packbf2(o[mi][nv][rh * 2], o[mi][nv][rh * 2 + 1]);
                        *(u32*)(opbase + (size_t)r * CCH + nv * 8 + 2 * qc) = pk;
                    }
                }
            }
    }
}

// ---------------------------------------------------------------------------
// Kernel 4: window reverse + unshift + residual + LN2 (float2-vectorized).
// ---------------------------------------------------------------------------
__global__ void reverse_add_ln2_kernel(const float* __restrict__ x,
                                       const float* __restrict__ g2,
                                       const float* __restrict__ b2) {
    int m = (blockIdx.x * blockDim.x + threadIdx.x) >> 5;
    int lane = threadIdx.x & 31;
    if (m >= MTOK) return;

    int wb  = m / NTOK;
    int n   = m - wb * NTOK;
    int bi  = wb >> 6;
    int win = wb & 63;
    int hs = (win >> 3) * WSZ + n / WSZ;
    int ws = (win & 7)  * WSZ + n % WSZ;
    int hh = hs + 3; if (hh >= 56) hh -= 56;
    int ww = ws + 3; if (ww >= 56) ww -= 56;
    size_t tt = (size_t)bi * 3136 + hh * 56 + ww;

    const float2* xs = (const float2*)(x + tt * CCH);
    const u32* pr = (const u32*)(g_proj + (size_t)m * CCH);
    float2* x2 = (float2*)(g_x2 + tt * CCH);
    u32* hl = (u32*)(g_ln2 + tt * CCH);

    float2 v[3];
    float s = 0.f;
#pragma unroll
    for (int i = 0; i < 3; i++) {
        int c2 = lane + 32 * i;
        float2 xv = xs[c2];
        u32 pp = pr[c2];
        __nv_bfloat162 pb = *(__nv_bfloat162*)&pp;
        v[i].x = xv.x + __bfloat162float(pb.x);
        v[i].y = xv.y + __bfloat162float(pb.y);
        x2[c2] = v[i];
        s += v[i].x + v[i].y;
    }
    s = warp_sum(s);
    float mu = s * (1.0f / CCH);
    float q = 0.f;
#pragma unroll
    for (int i = 0; i < 3; i++) {
        float dx = v[i].x - mu, dy = v[i].y - mu;
        q += dx * dx + dy * dy;
    }
    q = warp_sum(q);
    float rstd = rsqrtf(q * (1.0f / CCH) + 1e-5f);

    const float2* g2v = (const float2*)g2;
    const float2* b2v = (const float2*)b2;
#pragma unroll
    for (int i = 0; i < 3; i++) {
        int c2 = lane + 32 * i;
        float2 gg = g2v[c2], bb = b2v[c2];
        hl[c2] = packbf2((v[i].x - mu) * rstd * gg.x + bb.x,
                         (v[i].y - mu) * rstd * gg.y + bb.y);
    }
}

// ---------------------------------------------------------------------------
// Host launcher
// ---------------------------------------------------------------------------
extern "C" void kernel_launch(void* const* d_in, const int* in_sizes, int n_in,
                              void* d_out, int out_size) {
    const float* x          = (const float*)d_in[0];
    const float* g1         = (const float*)d_in[1];
    const float* b1         = (const float*)d_in[2];
    const float* qkv_w      = (const float*)d_in[3];
    const float* qkv_b      = (const float*)d_in[4];
    const float* proj_w     = (const float*)d_in[5];
    const float* proj_b     = (const float*)d_in[6];
    const float* bias_table = (const float*)d_in[7];
    const float* g2         = (const float*)d_in[8];
    const float* b2         = (const float*)d_in[9];
    const float* fc1_w      = (const float*)d_in[10];
    const float* fc1_b      = (const float*)d_in[11];
    const float* fc2_w      = (const float*)d_in[12];
    const float* fc2_b      = (const float*)d_in[13];
    float* out = (float*)d_out;

    bf16 *p_ln1, *p_qkvb, *p_att, *p_proj, *p_ln2, *p_hid, *p_wq, *p_wp, *p_w1, *p_w2;
    float *p_x2, *p_qbias;
    cudaGetSymbolAddress((void**)&p_ln1,  g_ln1);
    cudaGetSymbolAddress((void**)&p_qkvb, g_qkv);
    cudaGetSymbolAddress((void**)&p_att,  g_att);
    cudaGetSymbolAddress((void**)&p_proj, g_proj);
    cudaGetSymbolAddress((void**)&p_x2,   g_x2);
    cudaGetSymbolAddress((void**)&p_ln2,  g_ln2);
    cudaGetSymbolAddress((void**)&p_hid,  g_hid);
    cudaGetSymbolAddress((void**)&p_wq,   g_wq);
    cudaGetSymbolAddress((void**)&p_wp,   g_wp);
    cudaGetSymbolAddress((void**)&p_w1,   g_w1);
    cudaGetSymbolAddress((void**)&p_w2,   g_w2);
    cudaGetSymbolAddress((void**)&p_qbias, g_qbias);

    const int SMEM2 = 2 * (128 + 96) * 72 * 2;   // 64512 bytes
    const int SMEM3 = 3 * (128 + 96) * 72 * 2;   // 96768 bytes
    cudaFuncSetAttribute(bf16_gemm_kernel<3, 0, bf16>,
                         cudaFuncAttributeMaxDynamicSharedMemorySize, SMEM3);
    cudaFuncSetAttribute(bf16_gemm_kernel<2, 0, bf16>,
                         cudaFuncAttributeMaxDynamicSharedMemorySize, SMEM2);
    cudaFuncSetAttribute(bf16_gemm_kernel<2, 1, bf16>,
                         cudaFuncAttributeMaxDynamicSharedMemorySize, SMEM2);
    cudaFuncSetAttribute(bf16_gemm_kernel<3, 2, float>,
                         cudaFuncAttributeMaxDynamicSharedMemorySize, SMEM3);

    convert_weights<<<576, 256>>>(qkv_w, qkv_b, proj_w, fc1_w, fc2_w);
    build_vt_kernel<<<dim3(64, NHEAD), 256>>>(bias_table);

    ln_shift_gather_kernel<<<MTOK / 8, 256>>>(x, g1, b1);

    // qkv: NS=3 (validated)
    bf16_gemm_kernel<3, 0, bf16><<<dim3(QKVC / 96, MTOK / 128), 256, SMEM3>>>(
        p_ln1, p_wq, p_qbias, p_qkvb, nullptr, MTOK, QKVC, CCH);

    attn_mma_kernel<<<dim3(MTOK / NTOK, NHEAD / 2), 64>>>();

    // proj: NS=2
    bf16_gemm_kernel<2, 0, bf16><<<dim3(CCH / 96, MTOK / 128), 256, SMEM2>>>(
        p_att, p_wp, proj_b, p_proj, nullptr, MTOK, CCH, CCH);

    reverse_add_ln2_kernel<<<MTOK / 8, 256>>>(x, g2, b2);

    // fc1: NS=2
    bf16_gemm_kernel<2, 1, bf16><<<dim3(HIDD / 96, MTOK / 128), 256, SMEM2>>>(
        p_ln2, p_w1, fc1_b, p_hid, nullptr, MTOK, HIDD, CCH);

    // fc2: NS=3 (isolated test; nk=12 deepest pipeline)
    bf16_gemm_kernel<3, 2, float><<<dim3(CCH / 96, MTOK / 128), 256, SMEM3>>>(
        p_hid, p_w2, fc2_b, out, p_x2, MTOK, CCH, HIDD);
}